// round 13
// baseline (speedup 1.0000x reference)
#include <cuda_runtime.h>

// FVSBN: out[b][n] = sum_{k<n} x[b][k] * W[n][k] + bias[n]
// B = 65536, D = 764. Strictly-lower-triangular masked GEMM, fp32.
//
// Strategy:
//  1) prep kernel: masked+padded W -> g_Wm[768][768] (zero for k>=n and pads).
//  2) tiled GEMM 128x128x16, 256 threads, 8x8 per-thread tile computed with
//     packed fma.rn.f32x2 (full-rate fp32 on sm_103a; scalar FFMA is half-rate).
//  3) triangular structure: column-tile j only needs k < (j+1)*128.

#define DIM   764
#define DP    768
#define BM    128
#define BN    128
#define BK    16
#define NTHR  256
#define LDSW  132   // BM + 4 pad

typedef unsigned long long ull;

__device__ __align__(16) float g_Wm[DP * DP];

__global__ void prep_wm(const float* __restrict__ W) {
    int idx = blockIdx.x * blockDim.x + threadIdx.x;
    if (idx >= DP * DP) return;
    int n = idx / DP;
    int k = idx - n * DP;
    float v = 0.0f;
    if (n < DIM && k < n) v = W[n * DIM + k];   // strict lower triangle
    g_Wm[idx] = v;
}

__device__ __forceinline__ void fma2(ull& d, ull a, ull b) {
    asm volatile("fma.rn.f32x2 %0, %1, %2, %0;" : "+l"(d) : "l"(a), "l"(b));
}
__device__ __forceinline__ ull dup2(float x) {
    ull r; unsigned xi = __float_as_uint(x);
    asm("mov.b64 %0, {%1, %1};" : "=l"(r) : "r"(xi));
    return r;
}
__device__ __forceinline__ void unpack2(ull v, float& lo, float& hi) {
    asm("mov.b64 {%0, %1}, %2;" : "=f"(lo), "=f"(hi) : "l"(v));
}

__global__ __launch_bounds__(NTHR, 2)
void fvsbn_gemm(const float* __restrict__ x,
                const float* __restrict__ bias,
                float* __restrict__ out,
                int Btot) {
    __shared__ __align__(16) float As[BK][LDSW];
    __shared__ __align__(16) float Bs[BK][LDSW];

    const int tid = threadIdx.x;
    const int n0  = blockIdx.x * BN;
    const int m0  = blockIdx.y * BM;

    // Triangular cutoff: this column tile only needs k < (j+1)*BN (padded W
    // is zero above/beyond, pads included).
    const int kend   = min((blockIdx.x + 1) * BN, DP);   // multiple of BK
    const int ktiles = kend / BK;

    const int tx = tid & 15;    // n direction (16)
    const int ty = tid >> 4;    // m direction (16)

    ull acc[8][4];
    #pragma unroll
    for (int i = 0; i < 8; ++i)
        #pragma unroll
        for (int j = 0; j < 4; ++j) acc[i][j] = 0ULL;

    // loader mapping (per pass of 256 threads -> 256 float4s, 2 passes):
    //   idx = tid + p*256; row = idx>>2 (0..127); kv = (idx&3)*4 (0,4,8,12)
    // consecutive tids walk K within a row -> coalesced 64B row segments.
    for (int kt = 0; kt < ktiles; ++kt) {
        const int k0 = kt * BK;
        #pragma unroll
        for (int p = 0; p < 2; ++p) {
            int idx = tid + p * NTHR;
            int row = idx >> 2;
            int kv  = (idx & 3) << 2;
            int kg  = k0 + kv;

            // A tile (x). DIM % 4 == 0, so kg < DIM implies kg..kg+3 valid.
            float4 va = make_float4(0.f, 0.f, 0.f, 0.f);
            int gm = m0 + row;
            if (kg < DIM && gm < Btot)
                va = *reinterpret_cast<const float4*>(x + (size_t)gm * DIM + kg);
            As[kv + 0][row] = va.x; As[kv + 1][row] = va.y;
            As[kv + 2][row] = va.z; As[kv + 3][row] = va.w;

            // B tile (masked W, padded to 768x768 -> no guards needed).
            int gn = n0 + row;  // < 768 always
            float4 vb = *reinterpret_cast<const float4*>(g_Wm + gn * DP + kg);
            Bs[kv + 0][row] = vb.x; Bs[kv + 1][row] = vb.y;
            Bs[kv + 2][row] = vb.z; Bs[kv + 3][row] = vb.w;
        }
        __syncthreads();

        #pragma unroll
        for (int k = 0; k < BK; ++k) {
            float4 a0 = *reinterpret_cast<const float4*>(&As[k][ty * 4]);
            float4 a1 = *reinterpret_cast<const float4*>(&As[k][64 + ty * 4]);
            ulonglong2 bb0 = *reinterpret_cast<const ulonglong2*>(&Bs[k][tx * 4]);
            ulonglong2 bb1 = *reinterpret_cast<const ulonglong2*>(&Bs[k][64 + tx * 4]);
            float av[8] = {a0.x, a0.y, a0.z, a0.w, a1.x, a1.y, a1.z, a1.w};
            #pragma unroll
            for (int i = 0; i < 8; ++i) {
                ull ad = dup2(av[i]);
                fma2(acc[i][0], ad, bb0.x);
                fma2(acc[i][1], ad, bb0.y);
                fma2(acc[i][2], ad, bb1.x);
                fma2(acc[i][3], ad, bb1.y);
            }
        }
        __syncthreads();
    }

    // Epilogue: unpack f32x2 accumulators, add bias, store (float2 when possible).
    #pragma unroll
    for (int i = 0; i < 8; ++i) {
        int ml = (i < 4) ? (ty * 4 + i) : (64 + ty * 4 + (i - 4));
        int gm = m0 + ml;
        if (gm >= Btot) continue;
        float* orow = out + (size_t)gm * DIM;
        #pragma unroll
        for (int jp = 0; jp < 4; ++jp) {
            float lo, hi;
            unpack2(acc[i][jp], lo, hi);
            int nl = (jp < 2) ? (tx * 4 + jp * 2) : (64 + tx * 4 + (jp - 2) * 2);
            int gn = n0 + nl;
            if (gn + 1 < DIM) {
                float2 v = make_float2(lo + __ldg(bias + gn),
                                       hi + __ldg(bias + gn + 1));
                *reinterpret_cast<float2*>(orow + gn) = v;
            } else if (gn < DIM) {
                orow[gn] = lo + __ldg(bias + gn);
            }
        }
    }
}

extern "C" void kernel_launch(void* const* d_in, const int* in_sizes, int n_in,
                              void* d_out, int out_size) {
    const float* x = (const float*)d_in[0];
    const float* W = (const float*)d_in[1];
    const float* b = (const float*)d_in[2];
    float* out = (float*)d_out;

    int Btot = in_sizes[0] / DIM;

    prep_wm<<<(DP * DP + 255) / 256, 256>>>(W);

    dim3 grid((DIM + BN - 1) / BN, (Btot + BM - 1) / BM);  // (6, 512)
    fvsbn_gemm<<<grid, NTHR>>>(x, b, out, Btot);
}

// round 14
// speedup vs baseline: 1.0028x; 1.0028x over previous
#include <cuda_runtime.h>

// FVSBN: out[b][n] = sum_{k<n} x[b][k] * W[n][k] + bias[n]
// B = 65536, D = 764. Strictly-lower-triangular masked GEMM, fp32.
//
// Strategy:
//  1) prep kernel: masked+padded W -> g_Wm[768][768] (zero for k>=n and pads).
//  2) tiled GEMM 128x128x16, 256 threads, 8x8 per-thread tile computed with
//     packed fma.rn.f32x2 (full-rate fp32 on sm_103a; scalar FFMA is half-rate).
//  3) triangular structure: column-tile j only needs k < (j+1)*128.

#define DIM   764
#define DP    768
#define BM    128
#define BN    128
#define BK    16
#define NTHR  256
#define LDSW  132   // BM + 4 pad

typedef unsigned long long ull;

__device__ __align__(16) float g_Wm[DP * DP];

__global__ void prep_wm(const float* __restrict__ W) {
    int idx = blockIdx.x * blockDim.x + threadIdx.x;
    if (idx >= DP * DP) return;
    int n = idx / DP;
    int k = idx - n * DP;
    float v = 0.0f;
    if (n < DIM && k < n) v = W[n * DIM + k];   // strict lower triangle
    g_Wm[idx] = v;
}

__device__ __forceinline__ void fma2(ull& d, ull a, ull b) {
    asm volatile("fma.rn.f32x2 %0, %1, %2, %0;" : "+l"(d) : "l"(a), "l"(b));
}
__device__ __forceinline__ ull dup2(float x) {
    ull r; unsigned xi = __float_as_uint(x);
    asm("mov.b64 %0, {%1, %1};" : "=l"(r) : "r"(xi));
    return r;
}
__device__ __forceinline__ void unpack2(ull v, float& lo, float& hi) {
    asm("mov.b64 {%0, %1}, %2;" : "=f"(lo), "=f"(hi) : "l"(v));
}

__global__ __launch_bounds__(NTHR, 2)
void fvsbn_gemm(const float* __restrict__ x,
                const float* __restrict__ bias,
                float* __restrict__ out,
                int Btot) {
    __shared__ __align__(16) float As[BK][LDSW];
    __shared__ __align__(16) float Bs[BK][LDSW];

    const int tid = threadIdx.x;
    const int n0  = blockIdx.x * BN;
    const int m0  = blockIdx.y * BM;

    // Triangular cutoff: this column tile only needs k < (j+1)*BN (padded W
    // is zero above/beyond, pads included).
    const int kend   = min((blockIdx.x + 1) * BN, DP);   // multiple of BK
    const int ktiles = kend / BK;

    const int tx = tid & 15;    // n direction (16)
    const int ty = tid >> 4;    // m direction (16)

    ull acc[8][4];
    #pragma unroll
    for (int i = 0; i < 8; ++i)
        #pragma unroll
        for (int j = 0; j < 4; ++j) acc[i][j] = 0ULL;

    // loader mapping (per pass of 256 threads -> 256 float4s, 2 passes):
    //   idx = tid + p*256; row = idx>>2 (0..127); kv = (idx&3)*4 (0,4,8,12)
    // consecutive tids walk K within a row -> coalesced 64B row segments.
    for (int kt = 0; kt < ktiles; ++kt) {
        const int k0 = kt * BK;
        #pragma unroll
        for (int p = 0; p < 2; ++p) {
            int idx = tid + p * NTHR;
            int row = idx >> 2;
            int kv  = (idx & 3) << 2;
            int kg  = k0 + kv;

            // A tile (x). DIM % 4 == 0, so kg < DIM implies kg..kg+3 valid.
            float4 va = make_float4(0.f, 0.f, 0.f, 0.f);
            int gm = m0 + row;
            if (kg < DIM && gm < Btot)
                va = *reinterpret_cast<const float4*>(x + (size_t)gm * DIM + kg);
            As[kv + 0][row] = va.x; As[kv + 1][row] = va.y;
            As[kv + 2][row] = va.z; As[kv + 3][row] = va.w;

            // B tile (masked W, padded to 768x768 -> no guards needed).
            int gn = n0 + row;  // < 768 always
            float4 vb = *reinterpret_cast<const float4*>(g_Wm + gn * DP + kg);
            Bs[kv + 0][row] = vb.x; Bs[kv + 1][row] = vb.y;
            Bs[kv + 2][row] = vb.z; Bs[kv + 3][row] = vb.w;
        }
        __syncthreads();

        #pragma unroll
        for (int k = 0; k < BK; ++k) {
            float4 a0 = *reinterpret_cast<const float4*>(&As[k][ty * 4]);
            float4 a1 = *reinterpret_cast<const float4*>(&As[k][64 + ty * 4]);
            ulonglong2 bb0 = *reinterpret_cast<const ulonglong2*>(&Bs[k][tx * 4]);
            ulonglong2 bb1 = *reinterpret_cast<const ulonglong2*>(&Bs[k][64 + tx * 4]);
            float av[8] = {a0.x, a0.y, a0.z, a0.w, a1.x, a1.y, a1.z, a1.w};
            #pragma unroll
            for (int i = 0; i < 8; ++i) {
                ull ad = dup2(av[i]);
                fma2(acc[i][0], ad, bb0.x);
                fma2(acc[i][1], ad, bb0.y);
                fma2(acc[i][2], ad, bb1.x);
                fma2(acc[i][3], ad, bb1.y);
            }
        }
        __syncthreads();
    }

    // Epilogue: unpack f32x2 accumulators, add bias, store (float2 when possible).
    #pragma unroll
    for (int i = 0; i < 8; ++i) {
        int ml = (i < 4) ? (ty * 4 + i) : (64 + ty * 4 + (i - 4));
        int gm = m0 + ml;
        if (gm >= Btot) continue;
        float* orow = out + (size_t)gm * DIM;
        #pragma unroll
        for (int jp = 0; jp < 4; ++jp) {
            float lo, hi;
            unpack2(acc[i][jp], lo, hi);
            int nl = (jp < 2) ? (tx * 4 + jp * 2) : (64 + tx * 4 + (jp - 2) * 2);
            int gn = n0 + nl;
            if (gn + 1 < DIM) {
                float2 v = make_float2(lo + __ldg(bias + gn),
                                       hi + __ldg(bias + gn + 1));
                *reinterpret_cast<float2*>(orow + gn) = v;
            } else if (gn < DIM) {
                orow[gn] = lo + __ldg(bias + gn);
            }
        }
    }
}

extern "C" void kernel_launch(void* const* d_in, const int* in_sizes, int n_in,
                              void* d_out, int out_size) {
    const float* x = (const float*)d_in[0];
    const float* W = (const float*)d_in[1];
    const float* b = (const float*)d_in[2];
    float* out = (float*)d_out;

    int Btot = in_sizes[0] / DIM;

    prep_wm<<<(DP * DP + 255) / 256, 256>>>(W);

    dim3 grid((DIM + BN - 1) / BN, (Btot + BM - 1) / BM);  // (6, 512)
    fvsbn_gemm<<<grid, NTHR>>>(x, b, out, Btot);
}